// round 3
// baseline (speedup 1.0000x reference)
#include <cuda_runtime.h>
#include <math.h>

// Fixed shape: H=1024, B=64, T=1024
#define BB 64
#define TS 1024
#define HS 1024
#define TT 16                 // t per CTA tile
#define NTL (TS / TT)         // 64 tiles per batch row
#define THREADS 512
#define HSTRIDE ((size_t)BB * TS)   // 65536 floats between consecutive h

// Deterministic per-tile partials: [B][NTL][H] = 16.8 MB
__device__ float g_partial[BB * NTL * HS];

__global__ void __launch_bounds__(THREADS, 2)
attn_main(const float* __restrict__ dh, const float* __restrict__ enc) {
    __shared__ float sA[TT][17];
    __shared__ float sB[TT][17];
    __shared__ float sC[TT][17];
    __shared__ float sS[TT], sM[TT], sInv[TT];

    const int tid = threadIdx.x;
    const int w   = tid >> 5;          // warp 0..15
    const int l   = tid & 31;
    const int tg  = l & 3;             // t-group within warp (4 t's each)
    const int hcw = l >> 2;            // h-chunk within warp 0..7
    const int hc  = w * 8 + hcw;       // h-chunk 0..127 (8 h each)
    const int h0  = hc * 8;

    const int b    = blockIdx.x >> 6;
    const int tile = blockIdx.x & (NTL - 1);
    const int t0   = tile * TT;

    // decoder_hidden slice for this thread's 8 h's -> registers
    float dhv[8];
    {
        const float4 d0 = *(const float4*)(dh + b * HS + h0);
        const float4 d1 = *(const float4*)(dh + b * HS + h0 + 4);
        dhv[0]=d0.x; dhv[1]=d0.y; dhv[2]=d0.z; dhv[3]=d0.w;
        dhv[4]=d1.x; dhv[5]=d1.y; dhv[6]=d1.z; dhv[7]=d1.w;
    }

    // ---- streaming load: 8 x LDG.128, fused dot + max/min partials ----
    const float* gp = enc + (size_t)h0 * HSTRIDE + (size_t)b * TS + t0 + tg * 4;
    float v[8][4];
    float sp[4] = {0.f, 0.f, 0.f, 0.f};
    float mx[4] = {-INFINITY, -INFINITY, -INFINITY, -INFINITY};
    float mn[4] = { INFINITY,  INFINITY,  INFINITY,  INFINITY};
    #pragma unroll
    for (int i = 0; i < 8; ++i) {
        const float4 q = __ldg((const float4*)(gp + (size_t)i * HSTRIDE));
        v[i][0] = q.x; v[i][1] = q.y; v[i][2] = q.z; v[i][3] = q.w;
        #pragma unroll
        for (int j = 0; j < 4; ++j) {
            sp[j] = fmaf(v[i][j], dhv[i], sp[j]);
            mx[j] = fmaxf(mx[j], v[i][j]);
            mn[j] = fminf(mn[j], v[i][j]);
        }
    }

    // reduce across the 8 h-chunks inside the warp (lanes differing in hcw)
    #pragma unroll
    for (int off = 4; off <= 16; off <<= 1) {
        #pragma unroll
        for (int j = 0; j < 4; ++j) {
            sp[j] += __shfl_xor_sync(0xffffffffu, sp[j], off);
            mx[j]  = fmaxf(mx[j], __shfl_xor_sync(0xffffffffu, mx[j], off));
            mn[j]  = fminf(mn[j], __shfl_xor_sync(0xffffffffu, mn[j], off));
        }
    }
    if (hcw == 0) {   // lanes 0..3, tg == l
        #pragma unroll
        for (int j = 0; j < 4; ++j) {
            sA[tg * 4 + j][w] = sp[j];
            sB[tg * 4 + j][w] = mx[j];
            sC[tg * 4 + j][w] = mn[j];
        }
    }
    __syncthreads();

    // combine 16 warp-partials: warp w owns t = w
    {
        float s  = sA[w][l & 15];
        float x  = sB[w][l & 15];
        float n  = sC[w][l & 15];
        #pragma unroll
        for (int off = 8; off; off >>= 1) {
            s += __shfl_xor_sync(0xffffffffu, s, off);
            x  = fmaxf(x, __shfl_xor_sync(0xffffffffu, x, off));
            n  = fminf(n, __shfl_xor_sync(0xffffffffu, n, off));
        }
        if (l == 0) {
            sS[w] = s;
            sM[w] = (s >= 0.0f) ? x * s : n * s;   // exact max_h(v*s)
        }
    }
    __syncthreads();

    // ---- exp on registers + denominator ----
    float st[4], Mt[4], ds[4] = {0.f, 0.f, 0.f, 0.f};
    #pragma unroll
    for (int j = 0; j < 4; ++j) { st[j] = sS[tg * 4 + j]; Mt[j] = sM[tg * 4 + j]; }
    #pragma unroll
    for (int i = 0; i < 8; ++i)
        #pragma unroll
        for (int j = 0; j < 4; ++j) {
            v[i][j] = __expf(fmaf(v[i][j], st[j], -Mt[j]));
            ds[j] += v[i][j];
        }
    #pragma unroll
    for (int off = 4; off <= 16; off <<= 1)
        #pragma unroll
        for (int j = 0; j < 4; ++j)
            ds[j] += __shfl_xor_sync(0xffffffffu, ds[j], off);
    if (hcw == 0)
        #pragma unroll
        for (int j = 0; j < 4; ++j) sA[tg * 4 + j][w] = ds[j];
    __syncthreads();
    {
        float d = sA[w][l & 15];
        #pragma unroll
        for (int off = 8; off; off >>= 1)
            d += __shfl_xor_sync(0xffffffffu, d, off);
        if (l == 0) sInv[w] = 1.0f / d;
    }
    __syncthreads();

    // ---- scale + per-h sum over the 16 t's ----
    float inv[4];
    #pragma unroll
    for (int j = 0; j < 4; ++j) inv[j] = sInv[tg * 4 + j];

    float a[8];
    #pragma unroll
    for (int i = 0; i < 8; ++i) {
        float t = v[i][0] * inv[0];
        t = fmaf(v[i][1], inv[1], t);
        t = fmaf(v[i][2], inv[2], t);
        a[i] = fmaf(v[i][3], inv[3], t);
    }
    // sum across the 4 t-group lanes sharing this h-set
    #pragma unroll
    for (int off = 1; off <= 2; off <<= 1)
        #pragma unroll
        for (int i = 0; i < 8; ++i)
            a[i] += __shfl_xor_sync(0xffffffffu, a[i], off);

    if (tg == 0) {
        float* pr = g_partial + ((size_t)b * NTL + tile) * HS + h0;
        float4 o0 = {a[0], a[1], a[2], a[3]};
        float4 o1 = {a[4], a[5], a[6], a[7]};
        *(float4*)pr       = o0;
        *(float4*)(pr + 4) = o1;
    }
}

// out[b,h] = sum over NTL tile-partials (deterministic order), float4-wide
__global__ void __launch_bounds__(256)
attn_reduce(float* __restrict__ out) {
    const int b = blockIdx.x;
    const int q = threadIdx.x;   // h-quad 0..255
    const float4* p = (const float4*)(g_partial + (size_t)b * NTL * HS) + q;
    float4 acc = {0.f, 0.f, 0.f, 0.f};
    #pragma unroll
    for (int t = 0; t < NTL; ++t) {
        const float4 x = __ldg(p + (size_t)t * (HS / 4));
        acc.x += x.x; acc.y += x.y; acc.z += x.z; acc.w += x.w;
    }
    ((float4*)out)[b * (HS / 4) + q] = acc;
}

extern "C" void kernel_launch(void* const* d_in, const int* in_sizes, int n_in,
                              void* d_out, int out_size) {
    const float* dh  = (const float*)d_in[0];
    const float* enc = (const float*)d_in[1];
    if (n_in >= 2 && in_sizes[0] > in_sizes[1]) {
        enc = (const float*)d_in[0];
        dh  = (const float*)d_in[1];
    }
    float* out = (float*)d_out;

    attn_main<<<BB * NTL, THREADS>>>(dh, enc);
    attn_reduce<<<BB, 256>>>(out);
}